// round 8
// baseline (speedup 1.0000x reference)
#include <cuda_runtime.h>
#include <cuda_fp16.h>
#include <cstdint>

// ---------------------------------------------------------------------------
// Char-LSTM via mma.sync (HMMA fp16 hi/lo split), two-group software pipeline.
// BATCH=512, UNITS=256, SEQ=1024.
//
// 16 clusters x 8 CTAs (grid=128), 512 thr/CTA, 1 CTA/SM.
//   cluster -> 32 batches, split into 2 groups of 16 (phase-pipelined).
//   CTA rank r -> 32 units = 128 gate cols. W_h B-frags register-resident.
// Per group per step: gemm (m16 x n128 x K256, 3-term fp16 hi/lo) ->
// gates SMEM -> cell -> h hi/lo st.async broadcast to 8 CTAs with mbarrier
// expect_tx(16KB) completion. Group A's broadcast latency hides under group
// B's gemm+cell. No barrier.cluster in the loop.
// ---------------------------------------------------------------------------

namespace {
constexpr int kSeq     = 1024;
constexpr int kThreads = 512;
constexpr float kScale = 64.0f;
constexpr float kInv   = 1.0f / 64.0f;

// A staging: per (group, buf, hi/lo): [16 batches][264 halfwords] (528 B rows)
constexpr uint32_t A_STRIDE = 528;
constexpr uint32_t A_ARR    = 16u * A_STRIDE;        // 8448
constexpr uint32_t GATES0   = 8u * A_ARR;            // 67584: [16 b][132 f32]
constexpr uint32_t GATES1   = GATES0 + A_ARR;        // 76032
constexpr uint32_t TOKOFF   = GATES0 + 2u * A_ARR;   // 84480: 2 x 32 int
constexpr uint32_t MBARB    = TOKOFF + 256;          // 84736: 4 mbars x 8B
constexpr uint32_t SMEM_BYTES = MBARB + 32;          // 84768
constexpr uint32_t kTx = 16384u;                     // bytes per group per step
}  // namespace

__device__ __forceinline__ uint32_t abase(int g, int q, int a) {
    return (uint32_t)((g * 2 + q) * 2 + a) * A_ARR;
}
__device__ __forceinline__ uint32_t mboff(int g, int q) {
    return MBARB + (uint32_t)(g * 2 + q) * 8u;
}

// ---------------- PTX helpers ----------------------------------------------
__device__ __forceinline__ uint32_t smem_u32(const void* p) {
    uint32_t a;
    asm("{ .reg .u64 t; cvta.to.shared.u64 t, %1; cvt.u32.u64 %0, t; }" : "=r"(a) : "l"(p));
    return a;
}
__device__ __forceinline__ uint32_t mapa_u32(uint32_t a, uint32_t r) {
    uint32_t o;
    asm("mapa.shared::cluster.u32 %0, %1, %2;" : "=r"(o) : "r"(a), "r"(r));
    return o;
}
__device__ __forceinline__ void cluster_sync_() {
    asm volatile("barrier.cluster.arrive.aligned;" ::: "memory");
    asm volatile("barrier.cluster.wait.aligned;" ::: "memory");
}
__device__ __forceinline__ uint32_t cta_rank_() {
    uint32_t r; asm("mov.u32 %0, %%cluster_ctarank;" : "=r"(r)); return r;
}
__device__ __forceinline__ void mbar_init_(uint32_t m, uint32_t c) {
    asm volatile("mbarrier.init.shared.b64 [%0], %1;" :: "r"(m), "r"(c) : "memory");
}
__device__ __forceinline__ void mbar_arm_(uint32_t m, uint32_t tx) {
    asm volatile("mbarrier.arrive.expect_tx.release.cta.shared::cta.b64 _, [%0], %1;"
                 :: "r"(m), "r"(tx) : "memory");
}
__device__ __forceinline__ void mbar_wait_(uint32_t m, uint32_t parity) {
    asm volatile(
        "{\n\t.reg .pred P;\n\t"
        "WL_%=:\n\t"
        "mbarrier.try_wait.parity.acquire.cluster.shared::cta.b64 P, [%0], %1, 0x989680;\n\t"
        "@!P bra WL_%=;\n\t}"
        :: "r"(m), "r"(parity) : "memory");
}
__device__ __forceinline__ void st_async_u32(uint32_t dst, uint32_t v, uint32_t mbar) {
    asm volatile("st.async.shared::cluster.mbarrier::complete_tx::bytes.b32 [%0], %1, [%2];"
                 :: "r"(dst), "r"(v), "r"(mbar) : "memory");
}
__device__ __forceinline__ void ldsm_x4_(uint32_t* r, uint32_t addr) {
    asm volatile("ldmatrix.sync.aligned.m8n8.x4.shared.b16 {%0,%1,%2,%3}, [%4];"
                 : "=r"(r[0]), "=r"(r[1]), "=r"(r[2]), "=r"(r[3]) : "r"(addr));
}
__device__ __forceinline__ void mma16816_(float* d, const uint32_t* a,
                                          uint32_t b0, uint32_t b1) {
    asm volatile(
        "mma.sync.aligned.m16n8k16.row.col.f32.f16.f16.f32 "
        "{%0,%1,%2,%3}, {%4,%5,%6,%7}, {%8,%9}, {%0,%1,%2,%3};"
        : "+f"(d[0]), "+f"(d[1]), "+f"(d[2]), "+f"(d[3])
        : "r"(a[0]), "r"(a[1]), "r"(a[2]), "r"(a[3]), "r"(b0), "r"(b1));
}
__device__ __forceinline__ void st_v2_(uint32_t addr, float x, float y) {
    asm volatile("st.shared.v2.f32 [%0], {%1, %2};" :: "r"(addr), "f"(x), "f"(y) : "memory");
}
__device__ __forceinline__ float sigf(float x) {
    return __fdividef(1.0f, 1.0f + __expf(-x));
}
__device__ __forceinline__ float tanhf_(float x) { return 2.0f * sigf(2.0f * x) - 1.0f; }
__device__ __forceinline__ uint32_t pack2h(float a, float b) {
    __half2 h = __floats2half2_rn(a, b);
    return *reinterpret_cast<uint32_t*>(&h);
}

extern __shared__ char smem_raw[];

__global__ __launch_bounds__(kThreads, 1) __cluster_dims__(8, 1, 1)
void lstm_pipe_kernel(const int*   __restrict__ tokens,  // [512,1024]
                      const float* __restrict__ Wx,      // [128,1024]
                      const float* __restrict__ Wh,      // [256,1024]
                      const float* __restrict__ bias,    // [1024]
                      const float* __restrict__ Wd,      // [256,128]
                      const float* __restrict__ bd,      // [128]
                      float*       __restrict__ out)     // [512,128]
{
    const int tid  = threadIdx.x;
    const int lane = tid & 31;
    const int warp = tid >> 5;
    const uint32_t rank = cta_rank_();
    const int bbase = (blockIdx.x >> 3) * 32;
    const uint32_t sbase = smem_u32(smem_raw);
    int* tk = reinterpret_cast<int*>(smem_raw + TOKOFF);

    // ---- zero all A buffers ----------------------------------------------
    for (uint32_t i = tid; i < GATES0 / 16u; i += kThreads)
        reinterpret_cast<uint4*>(smem_raw)[i] = make_uint4(0, 0, 0, 0);

    // ---- mbarriers: init count=1, arm expect_tx for first phases ----------
    if (tid == 0) {
#pragma unroll
        for (int m = 0; m < 4; ++m) mbar_init_(sbase + MBARB + m * 8, 1);
    }
    __syncthreads();
    if (tid == 0) {
#pragma unroll
        for (int m = 0; m < 4; ++m) mbar_arm_(sbase + MBARB + m * 8, kTx);
    }

    // ---- W_h B-fragments (register-resident, hi/lo, lo scaled x64) -------
    uint32_t wh[32], wl[32];
    {
        int n = warp * 8 + (lane >> 2);
        int gc = ((n >> 5) << 8) + (int)rank * 32 + (n & 31);
#pragma unroll
        for (int kt = 0; kt < 16; ++kt) {
            int k0 = kt * 16 + (lane & 3) * 2;
#pragma unroll
            for (int j = 0; j < 2; ++j) {
                float w0 = Wh[(k0 + 8 * j) * 1024 + gc];
                float w1 = Wh[(k0 + 8 * j + 1) * 1024 + gc];
                float h0 = __half2float(__float2half_rn(w0));
                float h1 = __half2float(__float2half_rn(w1));
                wh[kt * 2 + j] = pack2h(h0, h1);
                wl[kt * 2 + j] = pack2h((w0 - h0) * kScale, (w1 - h1) * kScale);
            }
        }
    }
    const int ncol0 = warp * 8 + (lane & 3) * 2;

    // ldmatrix per-lane offset within an A array (m16k16 tile)
    const uint32_t aoff =
        (uint32_t)((((lane >> 3) & 1) * 8 + (lane & 7)) * A_STRIDE +
                   ((lane >> 4) & 1) * 16);

    // ---- cell constants (threads 0..255): batch b in group, unit pair up --
    const int b  = tid & 15;
    const int up = (tid >> 4) & 15;
    float2 bs[4];
    if (tid < 256) {
#pragma unroll
        for (int g4 = 0; g4 < 4; ++g4)
            bs[g4] = *reinterpret_cast<const float2*>(
                bias + g4 * 256 + (int)rank * 32 + 2 * up);
    }
    float cst[2][2] = {{0.f, 0.f}, {0.f, 0.f}};

    uint32_t peer[8];
#pragma unroll
    for (int r = 0; r < 8; ++r) peer[r] = mapa_u32(sbase, (uint32_t)r);

    if (tid < 32) tk[tid] = tokens[(bbase + tid) * kSeq];
    __syncthreads();
    cluster_sync_();   // mbars + zeroed buffers visible cluster-wide

    for (int t = 0; t < kSeq; ++t) {
        if (tid < 32 && t + 1 < kSeq)
            tk[((t + 1) & 1) * 32 + tid] = tokens[(bbase + tid) * kSeq + (t + 1)];

        const int q_r = (t + 1) & 1;   // read buffer == (t-1)&1
        const int q_w = t & 1;         // write buffer

#pragma unroll
        for (int g = 0; g < 2; ++g) {
            // ---- wait group's h(t-1) delivered; re-arm this mbar ----------
            if (t > 0) {
                uint32_t mb = sbase + mboff(g, q_r);
                mbar_wait_(mb, (uint32_t)(((t - 1) >> 1) & 1));
                if (tid == 0 && t <= kSeq - 2) mbar_arm_(mb, kTx);
            }

            // ---- Wx gather + bias fold (cell threads; hides under gemm) --
            float2 wxb[4];
            if (tid < 256) {
                int tokb = tk[q_w * 32 + g * 16 + b];
                const float* wxp = Wx + tokb * 1024 + (int)rank * 32 + 2 * up;
#pragma unroll
                for (int g4 = 0; g4 < 4; ++g4) {
                    float2 w = *reinterpret_cast<const float2*>(wxp + g4 * 256);
                    wxb[g4] = make_float2(w.x + bs[g4].x, w.y + bs[g4].y);
                }
            }

            // ---- gemm: m16 x n8/warp x K256, 3 terms ----------------------
            float aA[4] = {0.f, 0.f, 0.f, 0.f};
            float aB[4] = {0.f, 0.f, 0.f, 0.f};
            const uint32_t hiB = sbase + abase(g, q_r, 0) + aoff;
            const uint32_t loB = hiB + A_ARR;
#pragma unroll
            for (int kt = 0; kt < 16; ++kt) {
                uint32_t ah[4], al[4];
                ldsm_x4_(ah, hiB + (uint32_t)(kt * 32));
                ldsm_x4_(al, loB + (uint32_t)(kt * 32));
                mma16816_(aA, ah, wh[2 * kt], wh[2 * kt + 1]);
                mma16816_(aB, al, wh[2 * kt], wh[2 * kt + 1]);
                mma16816_(aB, ah, wl[2 * kt], wl[2 * kt + 1]);
            }

            // ---- gates[b][col] = aA + aB/64 (bias added in cell) ----------
            const uint32_t gOff = g ? GATES1 : GATES0;
            {
                int r0 = lane >> 2;
                uint32_t gb = sbase + gOff + (uint32_t)(ncol0 * 4);
                st_v2_(gb + (uint32_t)(r0 * 528),
                       fmaf(aB[0], kInv, aA[0]), fmaf(aB[1], kInv, aA[1]));
                st_v2_(gb + (uint32_t)((r0 + 8) * 528),
                       fmaf(aB[2], kInv, aA[2]), fmaf(aB[3], kInv, aA[3]));
            }
            __syncthreads();

            // ---- LSTM cell + st.async broadcast ---------------------------
            if (tid < 256) {
                const float2* gp2 = reinterpret_cast<const float2*>(
                    smem_raw + gOff + (uint32_t)(b * 528));
                float2 gi2 = gp2[up];
                float2 gj2 = gp2[up + 16];
                float2 gf2 = gp2[up + 32];
                float2 go2 = gp2[up + 48];
                float hv[2];
#pragma unroll
                for (int q2 = 0; q2 < 2; ++q2) {
                    float gi = (q2 ? gi2.y : gi2.x) + (q2 ? wxb[0].y : wxb[0].x);
                    float gj = (q2 ? gj2.y : gj2.x) + (q2 ? wxb[1].y : wxb[1].x);
                    float gf = (q2 ? gf2.y : gf2.x) + (q2 ? wxb[2].y : wxb[2].x);
                    float go = (q2 ? go2.y : go2.x) + (q2 ? wxb[3].y : wxb[3].x);
                    float& cs = cst[g][q2];
                    cs = cs * sigf(gf + 1.0f) + sigf(gi) * tanhf_(gj);
                    hv[q2] = tanhf_(cs) * sigf(go);
                }
                float h0 = __half2float(__float2half_rn(hv[0]));
                float h1 = __half2float(__float2half_rn(hv[1]));
                uint32_t whi = pack2h(h0, h1);
                uint32_t wlo = pack2h((hv[0] - h0) * kScale, (hv[1] - h1) * kScale);
                // global unit = rank*32 + 2up  -> halfword offset in row
                uint32_t offH = abase(g, q_w, 0) +
                                (uint32_t)(b * 528 + (int)rank * 64 + 4 * up);
                uint32_t offL = offH + A_ARR;
                uint32_t mbo  = mboff(g, q_w);
#pragma unroll
                for (int r = 0; r < 8; ++r) {
                    st_async_u32(peer[r] + offH, whi, peer[r] + mbo);
                    st_async_u32(peer[r] + offL, wlo, peer[r] + mbo);
                }
            }
        }  // group
    }  // t

    // ---- drain final h (step 1023 -> buf 1) -------------------------------
    mbar_wait_(sbase + mboff(0, 1), 1u);
    mbar_wait_(sbase + mboff(1, 1), 1u);
    __syncthreads();

    // ---- dense epilogue: out[b,:] = h @ Wd + bd ---------------------------
    {
        float* wds = reinterpret_cast<float*>(smem_raw + GATES0);   // 16KB
        for (int idx = tid; idx < 256 * 16; idx += kThreads)
            wds[idx] = Wd[(idx >> 4) * 128 + (int)rank * 16 + (idx & 15)];
        __syncthreads();

        int coli = tid & 15, bb = tid >> 4;        // bb: cluster batch 0..31
        int gsel = bb >> 4, row = bb & 15;
        const __half* hh = reinterpret_cast<const __half*>(
            smem_raw + abase(gsel, 1, 0) + (uint32_t)(row * 528));
        const __half* hl = reinterpret_cast<const __half*>(
            smem_raw + abase(gsel, 1, 1) + (uint32_t)(row * 528));
        int colr = (int)rank * 16 + coli;
        float acc = bd[colr];
#pragma unroll 8
        for (int u = 0; u < 256; ++u) {
            float h = __half2float(hh[u]) + __half2float(hl[u]) * kInv;
            acc += h * wds[u * 16 + coli];
        }
        out[(bbase + bb) * 128 + colr] = acc;
    }
    cluster_sync_();
}

extern "C" void kernel_launch(void* const* d_in, const int* in_sizes, int n_in,
                              void* d_out, int out_size) {
    (void)in_sizes; (void)n_in; (void)out_size;
    const int*   tokens = (const int*)d_in[0];
    const float* Wx     = (const float*)d_in[1];
    const float* Wh     = (const float*)d_in[2];
    const float* b      = (const float*)d_in[3];
    const float* Wd     = (const float*)d_in[4];
    const float* bd     = (const float*)d_in[5];
    float* out = (float*)d_out;

    cudaFuncSetAttribute(lstm_pipe_kernel,
                         cudaFuncAttributeMaxDynamicSharedMemorySize,
                         (int)SMEM_BYTES);
    lstm_pipe_kernel<<<128, kThreads, SMEM_BYTES>>>(tokens, Wx, Wh, b, Wd, bd, out);
}

// round 9
// speedup vs baseline: 3.1263x; 3.1263x over previous
#include <cuda_runtime.h>
#include <cuda_fp16.h>
#include <cstdint>

// ---------------------------------------------------------------------------
// Char-LSTM via mma.sync (HMMA fp16 hi/lo split). BATCH=512, UNITS=256, SEQ=1024.
//
// 32 clusters x 4 CTAs (grid=128), 512 thr/CTA, 1 CTA/SM.
//   cluster -> 16 batches; CTA rank r -> 64 units = 256 gate cols.
//   warp w (0..15) -> units 4w..4w+3 (2 n8-tiles, col = gate*2 + unit).
// W_hi B-frags register-resident (64 regs/warp); W_lo in SMEM via ldmatrix.
// gates = Ahi*Whi + (Alo*Whi + Ahi*Wlo)/64  (A = h fp16 hi/lo, lo scaled x64).
// Cell computed IN REGISTERS after a 4-shuffle quad transpose of the
// accumulators (no gates SMEM round-trip, no __syncthreads in the loop).
// h hi/lo broadcast to 4 cluster CTAs via st.shared::cluster.v2;
// one barrier.cluster per step; double-buffered A staging.
// ---------------------------------------------------------------------------

namespace {
constexpr int kSeq     = 1024;
constexpr int kThreads = 512;
constexpr float kScale = 64.0f;
constexpr float kInv   = 1.0f / 64.0f;

// SMEM map
constexpr uint32_t WLO      = 0;                     // W_lo [256 n][k] 528B rows
constexpr uint32_t WLO_SIZE = 256u * 528u;           // 135168
constexpr uint32_t ABASE    = WLO_SIZE;              // h staging, 2 bufs x (hi+lo)
constexpr uint32_t A_ROW    = 528;                   // 16 batches x 264 halves
constexpr uint32_t A_ARR    = 16u * A_ROW;           // 8448
constexpr uint32_t A_BUF    = 2u * A_ARR;            // 16896 (hi then lo)
constexpr uint32_t SMEM_BYTES = ABASE + 2u * A_BUF;  // 168960
}  // namespace

// ---------------- PTX helpers ----------------------------------------------
__device__ __forceinline__ uint32_t smem_u32(const void* p) {
    uint32_t a;
    asm("{ .reg .u64 t; cvta.to.shared.u64 t, %1; cvt.u32.u64 %0, t; }" : "=r"(a) : "l"(p));
    return a;
}
__device__ __forceinline__ uint32_t mapa_u32(uint32_t a, uint32_t r) {
    uint32_t o;
    asm("mapa.shared::cluster.u32 %0, %1, %2;" : "=r"(o) : "r"(a), "r"(r));
    return o;
}
__device__ __forceinline__ void st_cluster_v2(uint32_t a, uint32_t v0, uint32_t v1) {
    asm volatile("st.shared::cluster.v2.b32 [%0], {%1, %2};"
                 :: "r"(a), "r"(v0), "r"(v1) : "memory");
}
__device__ __forceinline__ void cluster_arrive_() {
    asm volatile("barrier.cluster.arrive.aligned;" ::: "memory");
}
__device__ __forceinline__ void cluster_wait_() {
    asm volatile("barrier.cluster.wait.aligned;" ::: "memory");
}
__device__ __forceinline__ uint32_t cta_rank_() {
    uint32_t r; asm("mov.u32 %0, %%cluster_ctarank;" : "=r"(r)); return r;
}
__device__ __forceinline__ void ldsm_x4_(uint32_t* r, uint32_t addr) {
    asm volatile("ldmatrix.sync.aligned.m8n8.x4.shared.b16 {%0,%1,%2,%3}, [%4];"
                 : "=r"(r[0]), "=r"(r[1]), "=r"(r[2]), "=r"(r[3]) : "r"(addr));
}
__device__ __forceinline__ void ldsm_x2_(uint32_t* r, uint32_t addr) {
    asm volatile("ldmatrix.sync.aligned.m8n8.x2.shared.b16 {%0,%1}, [%2];"
                 : "=r"(r[0]), "=r"(r[1]) : "r"(addr));
}
__device__ __forceinline__ void mma16816_(float* d, const uint32_t* a,
                                          uint32_t b0, uint32_t b1) {
    asm volatile(
        "mma.sync.aligned.m16n8k16.row.col.f32.f16.f16.f32 "
        "{%0,%1,%2,%3}, {%4,%5,%6,%7}, {%8,%9}, {%0,%1,%2,%3};"
        : "+f"(d[0]), "+f"(d[1]), "+f"(d[2]), "+f"(d[3])
        : "r"(a[0]), "r"(a[1]), "r"(a[2]), "r"(a[3]), "r"(b0), "r"(b1));
}
__device__ __forceinline__ float sigf(float x) {
    return __fdividef(1.0f, 1.0f + __expf(-x));
}
__device__ __forceinline__ float tanhf_(float x) { return 2.0f * sigf(2.0f * x) - 1.0f; }
__device__ __forceinline__ uint32_t pack2h(float a, float b) {
    __half2 h = __floats2half2_rn(a, b);
    return *reinterpret_cast<uint32_t*>(&h);
}
// 4x4 transpose within a quad: after, lane m holds reg[k] = original reg m
// of quad lane k.
__device__ __forceinline__ void quad_transpose(float g[4], int m) {
    float s0 = (m & 1) ? g[0] : g[1];
    float s1 = (m & 1) ? g[2] : g[3];
    s0 = __shfl_xor_sync(0xffffffffu, s0, 1);
    s1 = __shfl_xor_sync(0xffffffffu, s1, 1);
    if (m & 1) { g[0] = s0; g[2] = s1; } else { g[1] = s0; g[3] = s1; }
    float t0 = (m & 2) ? g[0] : g[2];
    float t1 = (m & 2) ? g[1] : g[3];
    t0 = __shfl_xor_sync(0xffffffffu, t0, 2);
    t1 = __shfl_xor_sync(0xffffffffu, t1, 2);
    if (m & 2) { g[0] = t0; g[1] = t1; } else { g[2] = t0; g[3] = t1; }
}

extern __shared__ char smem_raw[];

__global__ __launch_bounds__(kThreads, 1) __cluster_dims__(4, 1, 1)
void lstm_quad_kernel(const int*   __restrict__ tokens,  // [512,1024]
                      const float* __restrict__ Wx,      // [128,1024]
                      const float* __restrict__ Wh,      // [256,1024]
                      const float* __restrict__ bias,    // [1024]
                      const float* __restrict__ Wd,      // [256,128]
                      const float* __restrict__ bd,      // [128]
                      float*       __restrict__ out)     // [512,128]
{
    const int tid  = threadIdx.x;
    const int lane = tid & 31;
    const int w    = tid >> 5;           // warp 0..15 -> units 4w..4w+3
    const int m    = lane & 3;           // quad slot
    const int p    = m & 1;              // unit parity of this lane's cells
    const int r    = (lane >> 2) + 8 * (m >> 1);   // batch row 0..15
    const uint32_t rank = cta_rank_();
    const int bbase = (blockIdx.x >> 2) * 16;
    const uint32_t sbase = smem_u32(smem_raw);

    // ---- zero A staging (both buffers) ------------------------------------
    for (uint32_t i = tid; i < (2u * A_BUF) / 16u; i += kThreads)
        reinterpret_cast<uint4*>(smem_raw + ABASE)[i] = make_uint4(0, 0, 0, 0);

    // ---- W_lo into SMEM: row n (0..255), k contiguous ----------------------
    // n -> warp w'=n>>4, tile j=(n>>3)&1, cc=n&7: gate=cc>>1, unit=4w'+2j+(cc&1)
    for (int idx = tid; idx < 256 * 256; idx += kThreads) {
        int n = idx >> 8, k = idx & 255;
        int gate = (n & 7) >> 1;
        int ul = 4 * (n >> 4) + 2 * ((n >> 3) & 1) + (n & 1);
        float v = Wh[k * 1024 + gate * 256 + (int)rank * 64 + ul];
        float h = __half2float(__float2half_rn(v));
        *reinterpret_cast<__half*>(smem_raw + WLO + n * 528 + k * 2) =
            __float2half_rn((v - h) * kScale);
    }

    // ---- W_hi B-fragments, register-resident (2 n-tiles x 32 regs) --------
    uint32_t wh0[32], wh1[32];
#pragma unroll
    for (int j = 0; j < 2; ++j) {
        int cc = lane >> 2;
        int ul = 4 * w + 2 * j + (cc & 1);
        int gc = (cc >> 1) * 256 + (int)rank * 64 + ul;
#pragma unroll
        for (int kt = 0; kt < 16; ++kt) {
            int k0 = kt * 16 + (lane & 3) * 2;
#pragma unroll
            for (int jj = 0; jj < 2; ++jj) {
                float a = Wh[(k0 + 8 * jj) * 1024 + gc];
                float b = Wh[(k0 + 8 * jj + 1) * 1024 + gc];
                uint32_t v = pack2h(__half2float(__float2half_rn(a)),
                                    __half2float(__float2half_rn(b)));
                if (j == 0) wh0[kt * 2 + jj] = v; else wh1[kt * 2 + jj] = v;
            }
        }
    }

    // ---- per-lane cell constants ------------------------------------------
    float bi[2][4];
#pragma unroll
    for (int j = 0; j < 2; ++j)
#pragma unroll
        for (int g = 0; g < 4; ++g)
            bi[j][g] = bias[g * 256 + (int)rank * 64 + 4 * w + 2 * j + p];
    float cst[2] = {0.f, 0.f};
    int tok_cur = tokens[(bbase + r) * kSeq];

    // ldmatrix lane address offsets
    const uint32_t aoff =
        (uint32_t)(((((lane >> 3) & 1) * 8) + (lane & 7)) * 528 +
                   ((lane >> 4) & 1) * 16);
    const uint32_t bloff0 = sbase + WLO +
        (uint32_t)((w * 16 + (lane & 7)) * 528 + ((lane >> 3) & 1) * 16);
    const uint32_t bloff1 = bloff0 + 8u * 528u;

    __syncthreads();
    cluster_arrive_(); cluster_wait_();   // zeroed staging visible cluster-wide

    for (int t = 0; t < kSeq; ++t) {
        const uint32_t q = (uint32_t)(t & 1);

        // ---- Wx gather (consumed post-gemm) + next-token prefetch --------
        float wx[2][4];
        {
            const float* wp = Wx + tok_cur * 1024 + (int)rank * 64 + 4 * w + p;
#pragma unroll
            for (int j = 0; j < 2; ++j)
#pragma unroll
                for (int g = 0; g < 4; ++g)
                    wx[j][g] = wp[g * 256 + 2 * j];
        }
        int tok_next = (t + 1 < kSeq) ? tokens[(bbase + r) * kSeq + t + 1] : 0;

        // ---- gemm: m16 x (2 x n8) x K256, 3-term hi/lo --------------------
        float aA0[4] = {0, 0, 0, 0}, aB0[4] = {0, 0, 0, 0};
        float aA1[4] = {0, 0, 0, 0}, aB1[4] = {0, 0, 0, 0};
        const uint32_t ahB = sbase + ABASE + q * A_BUF + aoff;
        const uint32_t alB = ahB + A_ARR;
#pragma unroll
        for (int kt = 0; kt < 16; ++kt) {
            const uint32_t ko = (uint32_t)(kt * 32);
            uint32_t ah[4], al[4], b0[2], b1[2];
            ldsm_x4_(ah, ahB + ko);
            ldsm_x4_(al, alB + ko);
            ldsm_x2_(b0, bloff0 + ko);
            ldsm_x2_(b1, bloff1 + ko);
            mma16816_(aA0, ah, wh0[2 * kt], wh0[2 * kt + 1]);
            mma16816_(aB0, al, wh0[2 * kt], wh0[2 * kt + 1]);
            mma16816_(aB0, ah, b0[0], b0[1]);
            mma16816_(aA1, ah, wh1[2 * kt], wh1[2 * kt + 1]);
            mma16816_(aB1, al, wh1[2 * kt], wh1[2 * kt + 1]);
            mma16816_(aB1, ah, b1[0], b1[1]);
        }

        // ---- combine, quad-transpose, cell (in registers) -----------------
        float hv[2];
#pragma unroll
        for (int j = 0; j < 2; ++j) {
            float g[4];
#pragma unroll
            for (int k = 0; k < 4; ++k)
                g[k] = j ? fmaf(aB1[k], kInv, aA1[k]) : fmaf(aB0[k], kInv, aA0[k]);
            quad_transpose(g, m);    // lane m: gates i,j,f,o for (row r, unit 4w+2j+p)
            float gi = g[0] + wx[j][0] + bi[j][0];
            float gj = g[1] + wx[j][1] + bi[j][1];
            float gf = g[2] + wx[j][2] + bi[j][2];
            float go = g[3] + wx[j][3] + bi[j][3];
            cst[j] = cst[j] * sigf(gf + 1.0f) + sigf(gi) * tanhf_(gj);
            hv[j] = tanhf_(cst[j]) * sigf(go);
        }

        // ---- pack unit-pairs, broadcast to 4 cluster CTAs ------------------
        {
            float hp0 = __shfl_xor_sync(0xffffffffu, hv[0], 1);
            float hp1 = __shfl_xor_sync(0xffffffffu, hv[1], 1);
            uint32_t v0, v1;
            if (p == 0) {            // even lanes carry hi halves (own=even unit)
                v0 = pack2h(hv[0], hp0);
                v1 = pack2h(hv[1], hp1);
            } else {                 // odd lanes carry scaled-lo halves
                float e0 = hp0 - __half2float(__float2half_rn(hp0));
                float o0 = hv[0] - __half2float(__float2half_rn(hv[0]));
                float e1 = hp1 - __half2float(__float2half_rn(hp1));
                float o1 = hv[1] - __half2float(__float2half_rn(hv[1]));
                v0 = pack2h(e0 * kScale, o0 * kScale);
                v1 = pack2h(e1 * kScale, o1 * kScale);
            }
            uint32_t off = ABASE + (q ^ 1u) * A_BUF + (p ? A_ARR : 0u) +
                           (uint32_t)(r * 528 + (int)rank * 128 + 8 * w);
#pragma unroll
            for (uint32_t pr = 0; pr < 4; ++pr)
                st_cluster_v2(mapa_u32(sbase, pr) + off, v0, v1);
        }

        cluster_arrive_();
        tok_cur = tok_next;
        cluster_wait_();
    }

    // ---- dense epilogue: out[b,:] = h @ Wd + bd ---------------------------
    // final h in buf0 (t=1023 wrote q^1 = 0). rank -> out cols [32r, 32r+32).
    {
        float* wds = reinterpret_cast<float*>(smem_raw + WLO);   // 32KB staging
        for (int idx = tid; idx < 256 * 32; idx += kThreads)
            wds[idx] = Wd[(idx >> 5) * 128 + (int)rank * 32 + (idx & 31)];
        __syncthreads();

        int ci = tid & 31, b = tid >> 5;           // b: 0..15
        int col = (int)rank * 32 + ci;
        const __half* hh = reinterpret_cast<const __half*>(
            smem_raw + ABASE + (uint32_t)(b * 528));
        const __half* hl = reinterpret_cast<const __half*>(
            smem_raw + ABASE + A_ARR + (uint32_t)(b * 528));
        float acc = bd[col];
#pragma unroll 8
        for (int u = 0; u < 256; ++u) {
            float h = __half2float(hh[u]) + __half2float(hl[u]) * kInv;
            acc += h * wds[u * 32 + ci];
        }
        out[(bbase + b) * 128 + col] = acc;
    }
    cluster_arrive_(); cluster_wait_();
}

extern "C" void kernel_launch(void* const* d_in, const int* in_sizes, int n_in,
                              void* d_out, int out_size) {
    (void)in_sizes; (void)n_in; (void)out_size;
    const int*   tokens = (const int*)d_in[0];
    const float* Wx     = (const float*)d_in[1];
    const float* Wh     = (const float*)d_in[2];
    const float* b      = (const float*)d_in[3];
    const float* Wd     = (const float*)d_in[4];
    const float* bd     = (const float*)d_in[5];
    float* out = (float*)d_out;

    cudaFuncSetAttribute(lstm_quad_kernel,
                         cudaFuncAttributeMaxDynamicSharedMemorySize,
                         (int)SMEM_BYTES);
    // 32 clusters of 4 CTAs (static __cluster_dims__), 1 CTA/SM.
    lstm_quad_kernel<<<128, kThreads, SMEM_BYTES>>>(tokens, Wx, Wh, b, Wd, bd, out);
}